// round 9
// baseline (speedup 1.0000x reference)
#include <cuda_runtime.h>
#include <cuda_bf16.h>
#include <cuda_fp16.h>
#include <math.h>
#include <cstdint>

#define N 4096
#define D 512
#define NN (N * N)

// log2-domain scale: (1/EPS) * log2(e)
#define KSCALE 14.4269504088896340736f
// EPS * ln2 / N
#define OUT_SCALE (0.1 * 0.69314718055994530942 / 4096.0)

// ---------------- device scratch (no allocations allowed) ----------------
__device__ __half d_ChXY[NN];
__device__ __half d_ChYX[NN];
__device__ __half d_ChXX[NN];
__device__ __half d_ChYY[NN];
__device__ float d_Ctmp[NN];
__device__ float d_colpart[512][N];   // per-band partial column sums (8MB)
__device__ int   d_rmin[4][N];    // float bits; 0=xy rows,1=xy cols(yx rows),2=xx,3=yy
__device__ float d_xsq[N];
__device__ float d_ysq[N];
__device__ float d_F[3][N];
__device__ float d_G[3][N];
__device__ float d_L[2][3][N];
__device__ __nv_bfloat16 d_xhi[N * D];
__device__ __nv_bfloat16 d_xlo[N * D];
__device__ __nv_bfloat16 d_yhi[N * D];
__device__ __nv_bfloat16 d_ylo[N * D];

__device__ __forceinline__ float ex2f(float x) {
    float y;
    asm("ex2.approx.ftz.f32 %0, %1;" : "=f"(y) : "f"(x));
    return y;
}

// ---------------- bf16 split conversion ----------------
__global__ void convert_kernel(const float* __restrict__ X,
                               __nv_bfloat16* __restrict__ hi,
                               __nv_bfloat16* __restrict__ lo) {
    int i = blockIdx.x * 256 + threadIdx.x;
    float v = X[i];
    __nv_bfloat16 h = __float2bfloat16_rn(v);
    float r = v - __bfloat162float(h);
    hi[i] = h;
    lo[i] = __float2bfloat16_rn(r);
}

// ---------------- row sum-of-squares (fp32 exact) ----------------
__global__ void rowsq_kernel(const float* __restrict__ X, float* __restrict__ out) {
    int row = blockIdx.x * 8 + threadIdx.y;
    const float* xr = X + (size_t)row * D;
    float s = 0.f;
    for (int k = threadIdx.x; k < D; k += 32) {
        float v = __ldg(xr + k);
        s = fmaf(v, v, s);
    }
    #pragma unroll
    for (int off = 16; off > 0; off >>= 1)
        s += __shfl_down_sync(0xffffffffu, s, off);
    if (threadIdx.x == 0) out[row] = s;
}

// ---------------- init min arrays ----------------
__global__ void init_min_kernel() {
    int i = blockIdx.x * 256 + threadIdx.x;
    if (i < 4 * N) (&d_rmin[0][0])[i] = 0x7F7FFFFF;   // max finite float
}

// ---------------- HMMA split-bf16 cost GEMM (+ row/col min) ----------------
#define NT 32
#define NTRI (NT * (NT + 1) / 2)   // 528
#define KC 32
#define SROW 40

__device__ __forceinline__ void mma_bf16(float* c, const uint32_t* a, const uint32_t* b) {
    asm volatile(
        "mma.sync.aligned.m16n8k16.row.col.f32.bf16.bf16.f32 "
        "{%0,%1,%2,%3}, {%4,%5,%6,%7}, {%8,%9}, {%0,%1,%2,%3};"
        : "+f"(c[0]), "+f"(c[1]), "+f"(c[2]), "+f"(c[3])
        : "r"(a[0]), "r"(a[1]), "r"(a[2]), "r"(a[3]), "r"(b[0]), "r"(b[1]));
}

template <bool SYM>
__global__ __launch_bounds__(256) void tc_gemm_kernel(
    const __nv_bfloat16* __restrict__ Ahi, const __nv_bfloat16* __restrict__ Alo,
    const __nv_bfloat16* __restrict__ Bhi, const __nv_bfloat16* __restrict__ Blo,
    const float* __restrict__ a2, const float* __restrict__ b2,
    float* __restrict__ Cout, int* __restrict__ rminArr, int* __restrict__ cminArr)
{
    int bx, by;
    if (SYM) {
        int idx = blockIdx.x;
        float disc = (float)((2 * NT + 1) * (2 * NT + 1) - 8 * idx);
        int b = (int)((2 * NT + 1 - sqrtf(disc)) * 0.5f);
        #pragma unroll 1
        while (b > 0 && b * NT - b * (b - 1) / 2 > idx) b--;
        #pragma unroll 1
        while ((b + 1) * NT - (b + 1) * b / 2 <= idx) b++;
        by = b;
        bx = by + (idx - (b * NT - b * (b - 1) / 2));
    } else {
        bx = blockIdx.x & (NT - 1);
        by = blockIdx.x >> 5;
    }

    __shared__ __align__(16) __nv_bfloat16 sAhi[128 * SROW];
    __shared__ __align__(16) __nv_bfloat16 sAlo[128 * SROW];
    __shared__ __align__(16) __nv_bfloat16 sBhi[128 * SROW];
    __shared__ __align__(16) __nv_bfloat16 sBlo[128 * SROW];
    __shared__ int sRmin[128], sCmin[128];

    const int tid = threadIdx.x;
    const int wid = tid >> 5;
    const int lane = tid & 31;
    const int g = lane >> 2;
    const int tg = lane & 3;
    const int wm = wid & 3;
    const int wn = wid >> 2;

    if (tid < 128) { sRmin[tid] = 0x7F7FFFFF; sCmin[tid] = 0x7F7FFFFF; }

    const int rowA = by * 128;
    const int rowB = bx * 128;

    float acc[2][8][4];
    #pragma unroll
    for (int mf = 0; mf < 2; mf++)
        #pragma unroll
        for (int nf = 0; nf < 8; nf++)
            #pragma unroll
            for (int q = 0; q < 4; q++) acc[mf][nf][q] = 0.f;

    for (int k0 = 0; k0 < D; k0 += KC) {
        __syncthreads();
        #pragma unroll
        for (int it = 0; it < 2; it++) {
            int u = tid + it * 256;
            int r = u >> 2;
            int seg = u & 3;
            const size_t goff = (size_t)r * D + k0 + seg * 8;
            const int soff = r * SROW + seg * 8;
            *(float4*)(sAhi + soff) = __ldg((const float4*)(Ahi + (size_t)rowA * D + goff));
            *(float4*)(sAlo + soff) = __ldg((const float4*)(Alo + (size_t)rowA * D + goff));
            *(float4*)(sBhi + soff) = __ldg((const float4*)(Bhi + (size_t)rowB * D + goff));
            *(float4*)(sBlo + soff) = __ldg((const float4*)(Blo + (size_t)rowB * D + goff));
        }
        __syncthreads();

        #pragma unroll
        for (int ks = 0; ks < 2; ks++) {
            const int kb = ks * 16;
            uint32_t ah[2][4], al[2][4];
            #pragma unroll
            for (int mf = 0; mf < 2; mf++) {
                const int r0 = wm * 32 + mf * 16 + g;
                const int c0 = kb + tg * 2;
                ah[mf][0] = *(const uint32_t*)(sAhi + r0 * SROW + c0);
                ah[mf][1] = *(const uint32_t*)(sAhi + (r0 + 8) * SROW + c0);
                ah[mf][2] = *(const uint32_t*)(sAhi + r0 * SROW + c0 + 8);
                ah[mf][3] = *(const uint32_t*)(sAhi + (r0 + 8) * SROW + c0 + 8);
                al[mf][0] = *(const uint32_t*)(sAlo + r0 * SROW + c0);
                al[mf][1] = *(const uint32_t*)(sAlo + (r0 + 8) * SROW + c0);
                al[mf][2] = *(const uint32_t*)(sAlo + r0 * SROW + c0 + 8);
                al[mf][3] = *(const uint32_t*)(sAlo + (r0 + 8) * SROW + c0 + 8);
            }
            #pragma unroll
            for (int nf = 0; nf < 8; nf++) {
                const int n0 = wn * 64 + nf * 8 + g;
                const int c0 = kb + tg * 2;
                uint32_t bh[2], bl[2];
                bh[0] = *(const uint32_t*)(sBhi + n0 * SROW + c0);
                bh[1] = *(const uint32_t*)(sBhi + n0 * SROW + c0 + 8);
                bl[0] = *(const uint32_t*)(sBlo + n0 * SROW + c0);
                bl[1] = *(const uint32_t*)(sBlo + n0 * SROW + c0 + 8);
                #pragma unroll
                for (int mf = 0; mf < 2; mf++) {
                    mma_bf16(acc[mf][nf], ah[mf], bh);
                    mma_bf16(acc[mf][nf], ah[mf], bl);
                    mma_bf16(acc[mf][nf], al[mf], bh);
                }
            }
        }
    }
    __syncthreads();

    // ---------------- epilogue: write fp32 Cs + track mins ----------------
    #pragma unroll
    for (int mf = 0; mf < 2; mf++) {
        const int rl0 = wm * 32 + mf * 16 + g;
        const int r0 = by * 128 + rl0;
        const int r1 = r0 + 8;
        const float a20 = __ldg(a2 + r0);
        const float a21 = __ldg(a2 + r1);
        float rm0 = __int_as_float(0x7F7FFFFF), rm1 = rm0;
        #pragma unroll
        for (int nf = 0; nf < 8; nf++) {
            const int cl = wn * 64 + nf * 8 + tg * 2;
            const int c0 = bx * 128 + cl;
            const float b20 = __ldg(b2 + c0);
            const float b21 = __ldg(b2 + c0 + 1);
            float v00 = fminf(fmaxf(a20 + b20 - 2.0f * acc[mf][nf][0], 0.f), 1.0e6f) * KSCALE;
            float v01 = fminf(fmaxf(a20 + b21 - 2.0f * acc[mf][nf][1], 0.f), 1.0e6f) * KSCALE;
            float v10 = fminf(fmaxf(a21 + b20 - 2.0f * acc[mf][nf][2], 0.f), 1.0e6f) * KSCALE;
            float v11 = fminf(fmaxf(a21 + b21 - 2.0f * acc[mf][nf][3], 0.f), 1.0e6f) * KSCALE;

            *(float2*)(Cout + (size_t)r0 * N + c0) = make_float2(v00, v01);
            *(float2*)(Cout + (size_t)r1 * N + c0) = make_float2(v10, v11);
            if (SYM && bx != by) {
                float* t0 = Cout + (size_t)c0 * N;
                float* t1 = Cout + (size_t)(c0 + 1) * N;
                t0[r0] = v00; t0[r1] = v10;
                t1[r0] = v01; t1[r1] = v11;
            }
            rm0 = fminf(rm0, fminf(v00, v01));
            rm1 = fminf(rm1, fminf(v10, v11));
            atomicMin(&sCmin[cl],     __float_as_int(fminf(v00, v10)));
            atomicMin(&sCmin[cl + 1], __float_as_int(fminf(v01, v11)));
        }
        atomicMin(&sRmin[rl0],     __float_as_int(rm0));
        atomicMin(&sRmin[rl0 + 8], __float_as_int(rm1));
    }
    __syncthreads();
    if (tid < 128) {
        atomicMin(&rminArr[rowA + tid], sRmin[tid]);
        atomicMin(&cminArr[rowB + tid], sCmin[tid]);
    }
}

// ---------------- quantize fp32 -> fp16 delta (+ optional transpose) -------
template <bool TRANS>
__global__ void quantize_kernel(const float* __restrict__ in,
                                const int* __restrict__ rminb,
                                const int* __restrict__ cminb,
                                __half* __restrict__ outN,
                                __half* __restrict__ outT)
{
    __shared__ float tile[32][33];
    const int x = blockIdx.x * 32 + threadIdx.x;
    #pragma unroll
    for (int k = 0; k < 4; k++) {
        int yy = blockIdx.y * 32 + threadIdx.y + k * 8;
        float v = __ldg(in + (size_t)yy * N + x);
        tile[threadIdx.y + k * 8][threadIdx.x] = v;
        float ref = __int_as_float(__ldg(rminb + yy));
        outN[(size_t)yy * N + x] = __float2half_rn(v - ref);
    }
    if (TRANS) {
        __syncthreads();
        const int xo = blockIdx.y * 32 + threadIdx.x;
        #pragma unroll
        for (int k = 0; k < 4; k++) {
            int yo = blockIdx.x * 32 + threadIdx.y + k * 8;
            float v = tile[threadIdx.x][threadIdx.y + k * 8];
            float ref = __int_as_float(__ldg(cminb + yo));
            outT[(size_t)yo * N + xo] = __float2half_rn(v - ref);
        }
    }
}

// ---------------- potential init ----------------
__global__ void init_pot_kernel() {
    int i = blockIdx.x * 256 + threadIdx.x;
    if (i < 3 * N) {
        (&d_F[0][0])[i] = 0.f;
        (&d_G[0][0])[i] = 0.f;
    }
}

// ---------------- matrix select ----------------
__device__ __forceinline__ void pick_mh(int p, int phase,
                                        const __half*& M, const int*& refb) {
    if (p == 0)      { M = (phase == 0) ? d_ChXY : d_ChYX; refb = (phase == 0) ? d_rmin[0] : d_rmin[1]; }
    else if (p == 1) { M = d_ChXX; refb = d_rmin[2]; }
    else             { M = d_ChYY; refb = d_rmin[3]; }
}

// ---------------- robust half-iteration (online max), fp16 matrix ----------
__device__ __forceinline__ void lse_up(float& m, float& s, float a) {
    if (a <= m) {
        s += ex2f(a - m);
    } else {
        s = fmaf(s, ex2f(m - a), 1.0f);
        m = a;
    }
}

__global__ __launch_bounds__(256) void lse_robust_kernel(int phase) {
    const int p = blockIdx.y;
    const __half* M; const int* refb;
    pick_mh(p, phase, M, refb);
    const float* vin = (phase == 0) ? d_G[p] : d_F[p];
    float* vout      = (phase == 0) ? d_F[p] : d_G[p];

    const int row = blockIdx.x;
    const float ref = __int_as_float(__ldg(refb + row));
    const int col = threadIdx.x * 16;

    float vvr[16];
    #pragma unroll
    for (int k = 0; k < 4; k++) {
        float4 t = __ldg((const float4*)(vin + col + k * 4));
        vvr[k * 4 + 0] = t.x - ref; vvr[k * 4 + 1] = t.y - ref;
        vvr[k * 4 + 2] = t.z - ref; vvr[k * 4 + 3] = t.w - ref;
    }

    const __half* Mr = M + (size_t)row * N + col;
    uint4 h0 = __ldg((const uint4*)Mr);
    uint4 h1 = __ldg((const uint4*)(Mr + 8));
    uint32_t w[8] = {h0.x, h0.y, h0.z, h0.w, h1.x, h1.y, h1.z, h1.w};

    float m = __int_as_float(0xff800000);
    float s = 0.f;
    #pragma unroll
    for (int q = 0; q < 8; q++) {
        float2 dd = __half22float2(*reinterpret_cast<__half2*>(&w[q]));
        lse_up(m, s, vvr[2 * q]     - dd.x);
        lse_up(m, s, vvr[2 * q + 1] - dd.y);
    }

    __shared__ float sm[256], ss[256];
    sm[threadIdx.x] = m;
    ss[threadIdx.x] = s;
    __syncthreads();
    for (int off = 128; off > 0; off >>= 1) {
        if (threadIdx.x < off) {
            float m1 = sm[threadIdx.x], s1 = ss[threadIdx.x];
            float m2 = sm[threadIdx.x + off], s2 = ss[threadIdx.x + off];
            float mm = fmaxf(m1, m2);
            sm[threadIdx.x] = mm;
            ss[threadIdx.x] = fmaf(s1, ex2f(m1 - mm), s2 * ex2f(m2 - mm));
        }
        __syncthreads();
    }
    if (threadIdx.x == 0) {
        // a = (v-ref)-(Cs-ref) = v-Cs: ref cancels; L = sm + log2(ss).
        float L = sm[0] + log2f(ss[0]);
        vout[row] = 12.0f - L;
        d_L[phase][p][row] = L;
    }
}

// ---------------- shared row-wise fast pass body ----------------
#define RPB 8

__device__ __forceinline__ void fast_row_pass(
    const __half* __restrict__ M, const int* __restrict__ refb,
    const float* __restrict__ vin, float* __restrict__ vout,
    float* __restrict__ Lrow, int row0)
{
    const int col = threadIdx.x * 16;

    float vv[16];
    #pragma unroll
    for (int k = 0; k < 4; k++) {
        float4 t = __ldg((const float4*)(vin + col + k * 4));
        vv[k * 4 + 0] = t.x; vv[k * 4 + 1] = t.y;
        vv[k * 4 + 2] = t.z; vv[k * 4 + 3] = t.w;
    }

    float Lp[RPB], s[RPB];
    #pragma unroll
    for (int r = 0; r < RPB; r++) {
        Lp[r] = Lrow[row0 + r];
        const float cr = Lp[r] + __int_as_float(__ldg(refb + row0 + r));
        const __half* Mr = M + (size_t)(row0 + r) * N + col;
        uint4 h0 = __ldg((const uint4*)Mr);
        uint4 h1 = __ldg((const uint4*)(Mr + 8));
        uint32_t w[8] = {h0.x, h0.y, h0.z, h0.w, h1.x, h1.y, h1.z, h1.w};
        float a0 = 0.f, a1 = 0.f;
        #pragma unroll
        for (int q = 0; q < 8; q++) {
            float2 dd = __half22float2(*reinterpret_cast<__half2*>(&w[q]));
            a0 += ex2f((vv[2 * q]     - cr) - dd.x);
            a1 += ex2f((vv[2 * q + 1] - cr) - dd.y);
        }
        s[r] = a0 + a1;
    }

    #pragma unroll
    for (int off = 16; off > 0; off >>= 1) {
        #pragma unroll
        for (int r = 0; r < RPB; r++)
            s[r] += __shfl_down_sync(0xffffffffu, s[r], off);
    }
    __shared__ float sw[RPB][8];
    const int lane = threadIdx.x & 31;
    const int wid  = threadIdx.x >> 5;
    if (lane == 0) {
        #pragma unroll
        for (int r = 0; r < RPB; r++) sw[r][wid] = s[r];
    }
    __syncthreads();
    if (threadIdx.x < RPB) {
        const int r = threadIdx.x;
        float S = 0.f;
        #pragma unroll
        for (int w2 = 0; w2 < 8; w2++) S += sw[r][w2];
        float Lnew = Lp[r] + log2f(S);
        vout[row0 + r] = 12.0f - Lnew;
        Lrow[row0 + r] = Lnew;
    }
}

// ---------------- fast phase 0 (rows of ChXY/ChXX/ChYY) ----------------
__global__ __launch_bounds__(256) void lse_fast0_kernel() {
    const int p = blockIdx.y;
    const __half* M; const int* refb;
    pick_mh(p, 0, M, refb);
    fast_row_pass(M, refb, d_G[p], d_F[p], d_L[0][p], blockIdx.x * RPB);
}

// ---------------- fast phase 1: p=1,2 rows + p=0 column partials ----------
__global__ __launch_bounds__(256) void fast_p1_kernel() {
    if (blockIdx.y < 2) {
        const int p = blockIdx.y + 1;
        const __half* M; const int* refb;
        pick_mh(p, 1, M, refb);
        fast_row_pass(M, refb, d_F[p], d_G[p], d_L[1][p], blockIdx.x * RPB);
        return;
    }
    // ---- column-accumulate band over ChXY: 8 rows, all 4096 cols ----
    __shared__ float us[8];
    const int row0 = blockIdx.x * 8;
    if (threadIdx.x < 8)
        us[threadIdx.x] = d_F[0][row0 + threadIdx.x]
                        - __int_as_float(d_rmin[0][row0 + threadIdx.x]);
    __syncthreads();

    const int c0 = threadIdx.x * 16;
    float w[16], acc[16];
    #pragma unroll
    for (int k = 0; k < 4; k++) {
        float4 t = __ldg((const float4*)(&d_L[1][0][c0 + k * 4]));
        w[k * 4 + 0] = -t.x; w[k * 4 + 1] = -t.y;
        w[k * 4 + 2] = -t.z; w[k * 4 + 3] = -t.w;
    }
    #pragma unroll
    for (int k = 0; k < 16; k++) acc[k] = 0.f;

    #pragma unroll
    for (int r = 0; r < 8; r++) {
        const float ur = us[r];
        const __half* Mr = d_ChXY + (size_t)(row0 + r) * N + c0;
        uint4 h0 = __ldg((const uint4*)Mr);
        uint4 h1 = __ldg((const uint4*)(Mr + 8));
        uint32_t ww[8] = {h0.x, h0.y, h0.z, h0.w, h1.x, h1.y, h1.z, h1.w};
        #pragma unroll
        for (int q = 0; q < 8; q++) {
            float2 dd = __half22float2(*reinterpret_cast<__half2*>(&ww[q]));
            acc[2 * q]     += ex2f((ur + w[2 * q])     - dd.x);
            acc[2 * q + 1] += ex2f((ur + w[2 * q + 1]) - dd.y);
        }
    }
    float* dst = &d_colpart[blockIdx.x][c0];
    #pragma unroll
    for (int k = 0; k < 4; k++)
        *(float4*)(dst + k * 4) = make_float4(acc[4 * k], acc[4 * k + 1],
                                              acc[4 * k + 2], acc[4 * k + 3]);
}

// ---------------- finalize p=0 phase 1 columns ----------------
__global__ __launch_bounds__(256) void col_fin_kernel() {
    const int c = blockIdx.x * 256 + threadIdx.x;
    float S = 0.f;
    #pragma unroll 8
    for (int b = 0; b < 512; b++) S += d_colpart[b][c];
    float Lnew = d_L[1][0][c] + log2f(S);
    d_G[0][c] = 12.0f - Lnew;
    d_L[1][0][c] = Lnew;
}

// ---------------- final scalar reduce ----------------
__global__ __launch_bounds__(256) void final_reduce_kernel(float* __restrict__ out) {
    __shared__ double sh[3][256];
    const int tid = threadIdx.x;
    double acc0 = 0.0, acc1 = 0.0, acc2 = 0.0;
    for (int j = tid; j < N; j += 256) {
        acc0 += (double)d_F[0][j] + (double)d_G[0][j];
        acc1 += (double)d_F[1][j] + (double)d_G[1][j];
        acc2 += (double)d_F[2][j] + (double)d_G[2][j];
    }
    sh[0][tid] = acc0; sh[1][tid] = acc1; sh[2][tid] = acc2;
    __syncthreads();
    for (int off = 128; off > 0; off >>= 1) {
        if (tid < off) {
            sh[0][tid] += sh[0][tid + off];
            sh[1][tid] += sh[1][tid + off];
            sh[2][tid] += sh[2][tid + off];
        }
        __syncthreads();
    }
    if (tid == 0) {
        double Sdiff = sh[0][0] - 0.5 * (sh[1][0] + sh[2][0]);
        double val = Sdiff * OUT_SCALE;
        out[0] = (float)(val > 0.0 ? val : 0.0);
    }
}

// ---------------- launch ----------------
extern "C" void kernel_launch(void* const* d_in, const int* in_sizes, int n_in,
                              void* d_out, int out_size)
{
    const float* x = (const float*)d_in[0];
    const float* y = (const float*)d_in[1];
    float* out = (float*)d_out;

    float *Ctmp, *xsq, *ysq;
    __half *ChXY, *ChYX, *ChXX, *ChYY;
    int *rminA;
    __nv_bfloat16 *xhi, *xlo, *yhi, *ylo;
    cudaGetSymbolAddress((void**)&Ctmp, d_Ctmp);
    cudaGetSymbolAddress((void**)&ChXY, d_ChXY);
    cudaGetSymbolAddress((void**)&ChYX, d_ChYX);
    cudaGetSymbolAddress((void**)&ChXX, d_ChXX);
    cudaGetSymbolAddress((void**)&ChYY, d_ChYY);
    cudaGetSymbolAddress((void**)&rminA, d_rmin);
    cudaGetSymbolAddress((void**)&xsq, d_xsq);
    cudaGetSymbolAddress((void**)&ysq, d_ysq);
    cudaGetSymbolAddress((void**)&xhi, d_xhi);
    cudaGetSymbolAddress((void**)&xlo, d_xlo);
    cudaGetSymbolAddress((void**)&yhi, d_yhi);
    cudaGetSymbolAddress((void**)&ylo, d_ylo);

    int* rmXY = rminA + 0 * N;
    int* rmYX = rminA + 1 * N;
    int* rmXX = rminA + 2 * N;
    int* rmYY = rminA + 3 * N;

    convert_kernel<<<(N * D) / 256, 256>>>(x, xhi, xlo);
    convert_kernel<<<(N * D) / 256, 256>>>(y, yhi, ylo);

    dim3 rsBlock(32, 8);
    rowsq_kernel<<<N / 8, rsBlock>>>(x, xsq);
    rowsq_kernel<<<N / 8, rsBlock>>>(y, ysq);

    init_min_kernel<<<(4 * N + 255) / 256, 256>>>();

    dim3 qGrid(N / 32, N / 32);
    dim3 qBlock(32, 8);

    tc_gemm_kernel<false><<<NT * NT, 256>>>(xhi, xlo, yhi, ylo, xsq, ysq, Ctmp, rmXY, rmYX);
    quantize_kernel<true><<<qGrid, qBlock>>>(Ctmp, rmXY, rmYX, ChXY, ChYX);

    tc_gemm_kernel<true><<<NTRI, 256>>>(xhi, xlo, xhi, xlo, xsq, xsq, Ctmp, rmXX, rmXX);
    quantize_kernel<false><<<qGrid, qBlock>>>(Ctmp, rmXX, nullptr, ChXX, nullptr);

    tc_gemm_kernel<true><<<NTRI, 256>>>(yhi, ylo, yhi, ylo, ysq, ysq, Ctmp, rmYY, rmYY);
    quantize_kernel<false><<<qGrid, qBlock>>>(Ctmp, rmYY, nullptr, ChYY, nullptr);

    init_pot_kernel<<<(3 * N + 255) / 256, 256>>>();

    dim3 rGrid(N, 3);
    dim3 fGrid(N / RPB, 3);
    const int WARMUP = 3;
    for (int it = 0; it < WARMUP; it++) {
        lse_robust_kernel<<<rGrid, 256>>>(0);
        lse_robust_kernel<<<rGrid, 256>>>(1);
    }
    for (int it = WARMUP; it < 50; it++) {
        lse_fast0_kernel<<<fGrid, 256>>>();
        fast_p1_kernel<<<fGrid, 256>>>();
        col_fin_kernel<<<N / 256, 256>>>();
    }

    final_reduce_kernel<<<1, 256>>>(out);
}

// round 10
// speedup vs baseline: 1.4284x; 1.4284x over previous
#include <cuda_runtime.h>
#include <cuda_bf16.h>
#include <cuda_fp16.h>
#include <math.h>
#include <cstdint>

#define N 4096
#define D 512
#define NN (N * N)

// log2-domain scale: (1/EPS) * log2(e)
#define KSCALE 14.4269504088896340736f
// EPS * ln2 / N
#define OUT_SCALE (0.1 * 0.69314718055994530942 / 4096.0)

// ---------------- device scratch (no allocations allowed) ----------------
__device__ __half d_ChXY[NN];
__device__ __half d_ChYX[NN];
__device__ __half d_ChXX[NN];
__device__ __half d_ChYY[NN];
__device__ float d_Ctmp[NN];
__device__ int   d_rmin[4][N];    // float bits; 0=xy rows,1=xy cols(yx rows),2=xx,3=yy
__device__ float d_xsq[N];
__device__ float d_ysq[N];
__device__ float d_F[3][N];
__device__ float d_G[3][N];
__device__ float d_L[2][3][N];
__device__ __nv_bfloat16 d_xhi[N * D];
__device__ __nv_bfloat16 d_xlo[N * D];
__device__ __nv_bfloat16 d_yhi[N * D];
__device__ __nv_bfloat16 d_ylo[N * D];

__device__ __forceinline__ float ex2f(float x) {
    float y;
    asm("ex2.approx.ftz.f32 %0, %1;" : "=f"(y) : "f"(x));
    return y;
}

// ---------------- bf16 split conversion ----------------
__global__ void convert_kernel(const float* __restrict__ X,
                               __nv_bfloat16* __restrict__ hi,
                               __nv_bfloat16* __restrict__ lo) {
    int i = blockIdx.x * 256 + threadIdx.x;
    float v = X[i];
    __nv_bfloat16 h = __float2bfloat16_rn(v);
    float r = v - __bfloat162float(h);
    hi[i] = h;
    lo[i] = __float2bfloat16_rn(r);
}

// ---------------- row sum-of-squares (fp32 exact) ----------------
__global__ void rowsq_kernel(const float* __restrict__ X, float* __restrict__ out) {
    int row = blockIdx.x * 8 + threadIdx.y;
    const float* xr = X + (size_t)row * D;
    float s = 0.f;
    for (int k = threadIdx.x; k < D; k += 32) {
        float v = __ldg(xr + k);
        s = fmaf(v, v, s);
    }
    #pragma unroll
    for (int off = 16; off > 0; off >>= 1)
        s += __shfl_down_sync(0xffffffffu, s, off);
    if (threadIdx.x == 0) out[row] = s;
}

// ---------------- init min arrays ----------------
__global__ void init_min_kernel() {
    int i = blockIdx.x * 256 + threadIdx.x;
    if (i < 4 * N) (&d_rmin[0][0])[i] = 0x7F7FFFFF;   // max finite float
}

// ---------------- HMMA split-bf16 cost GEMM (+ row/col min) ----------------
#define NT 32
#define NTRI (NT * (NT + 1) / 2)   // 528
#define KC 32
#define SROW 40

__device__ __forceinline__ void mma_bf16(float* c, const uint32_t* a, const uint32_t* b) {
    asm volatile(
        "mma.sync.aligned.m16n8k16.row.col.f32.bf16.bf16.f32 "
        "{%0,%1,%2,%3}, {%4,%5,%6,%7}, {%8,%9}, {%0,%1,%2,%3};"
        : "+f"(c[0]), "+f"(c[1]), "+f"(c[2]), "+f"(c[3])
        : "r"(a[0]), "r"(a[1]), "r"(a[2]), "r"(a[3]), "r"(b[0]), "r"(b[1]));
}

template <bool SYM>
__global__ __launch_bounds__(256) void tc_gemm_kernel(
    const __nv_bfloat16* __restrict__ Ahi, const __nv_bfloat16* __restrict__ Alo,
    const __nv_bfloat16* __restrict__ Bhi, const __nv_bfloat16* __restrict__ Blo,
    const float* __restrict__ a2, const float* __restrict__ b2,
    float* __restrict__ Cout, int* __restrict__ rminArr, int* __restrict__ cminArr)
{
    int bx, by;
    if (SYM) {
        int idx = blockIdx.x;
        float disc = (float)((2 * NT + 1) * (2 * NT + 1) - 8 * idx);
        int b = (int)((2 * NT + 1 - sqrtf(disc)) * 0.5f);
        #pragma unroll 1
        while (b > 0 && b * NT - b * (b - 1) / 2 > idx) b--;
        #pragma unroll 1
        while ((b + 1) * NT - (b + 1) * b / 2 <= idx) b++;
        by = b;
        bx = by + (idx - (b * NT - b * (b - 1) / 2));
    } else {
        bx = blockIdx.x & (NT - 1);
        by = blockIdx.x >> 5;
    }

    __shared__ __align__(16) __nv_bfloat16 sAhi[128 * SROW];
    __shared__ __align__(16) __nv_bfloat16 sAlo[128 * SROW];
    __shared__ __align__(16) __nv_bfloat16 sBhi[128 * SROW];
    __shared__ __align__(16) __nv_bfloat16 sBlo[128 * SROW];
    __shared__ int sRmin[128], sCmin[128];

    const int tid = threadIdx.x;
    const int wid = tid >> 5;
    const int lane = tid & 31;
    const int g = lane >> 2;
    const int tg = lane & 3;
    const int wm = wid & 3;
    const int wn = wid >> 2;

    if (tid < 128) { sRmin[tid] = 0x7F7FFFFF; sCmin[tid] = 0x7F7FFFFF; }

    const int rowA = by * 128;
    const int rowB = bx * 128;

    float acc[2][8][4];
    #pragma unroll
    for (int mf = 0; mf < 2; mf++)
        #pragma unroll
        for (int nf = 0; nf < 8; nf++)
            #pragma unroll
            for (int q = 0; q < 4; q++) acc[mf][nf][q] = 0.f;

    for (int k0 = 0; k0 < D; k0 += KC) {
        __syncthreads();
        #pragma unroll
        for (int it = 0; it < 2; it++) {
            int u = tid + it * 256;
            int r = u >> 2;
            int seg = u & 3;
            const size_t goff = (size_t)r * D + k0 + seg * 8;
            const int soff = r * SROW + seg * 8;
            *(float4*)(sAhi + soff) = __ldg((const float4*)(Ahi + (size_t)rowA * D + goff));
            *(float4*)(sAlo + soff) = __ldg((const float4*)(Alo + (size_t)rowA * D + goff));
            *(float4*)(sBhi + soff) = __ldg((const float4*)(Bhi + (size_t)rowB * D + goff));
            *(float4*)(sBlo + soff) = __ldg((const float4*)(Blo + (size_t)rowB * D + goff));
        }
        __syncthreads();

        #pragma unroll
        for (int ks = 0; ks < 2; ks++) {
            const int kb = ks * 16;
            uint32_t ah[2][4], al[2][4];
            #pragma unroll
            for (int mf = 0; mf < 2; mf++) {
                const int r0 = wm * 32 + mf * 16 + g;
                const int c0 = kb + tg * 2;
                ah[mf][0] = *(const uint32_t*)(sAhi + r0 * SROW + c0);
                ah[mf][1] = *(const uint32_t*)(sAhi + (r0 + 8) * SROW + c0);
                ah[mf][2] = *(const uint32_t*)(sAhi + r0 * SROW + c0 + 8);
                ah[mf][3] = *(const uint32_t*)(sAhi + (r0 + 8) * SROW + c0 + 8);
                al[mf][0] = *(const uint32_t*)(sAlo + r0 * SROW + c0);
                al[mf][1] = *(const uint32_t*)(sAlo + (r0 + 8) * SROW + c0);
                al[mf][2] = *(const uint32_t*)(sAlo + r0 * SROW + c0 + 8);
                al[mf][3] = *(const uint32_t*)(sAlo + (r0 + 8) * SROW + c0 + 8);
            }
            #pragma unroll
            for (int nf = 0; nf < 8; nf++) {
                const int n0 = wn * 64 + nf * 8 + g;
                const int c0 = kb + tg * 2;
                uint32_t bh[2], bl[2];
                bh[0] = *(const uint32_t*)(sBhi + n0 * SROW + c0);
                bh[1] = *(const uint32_t*)(sBhi + n0 * SROW + c0 + 8);
                bl[0] = *(const uint32_t*)(sBlo + n0 * SROW + c0);
                bl[1] = *(const uint32_t*)(sBlo + n0 * SROW + c0 + 8);
                #pragma unroll
                for (int mf = 0; mf < 2; mf++) {
                    mma_bf16(acc[mf][nf], ah[mf], bh);
                    mma_bf16(acc[mf][nf], ah[mf], bl);
                    mma_bf16(acc[mf][nf], al[mf], bh);
                }
            }
        }
    }
    __syncthreads();

    // ---------------- epilogue: write fp32 Cs + track mins ----------------
    #pragma unroll
    for (int mf = 0; mf < 2; mf++) {
        const int rl0 = wm * 32 + mf * 16 + g;
        const int r0 = by * 128 + rl0;
        const int r1 = r0 + 8;
        const float a20 = __ldg(a2 + r0);
        const float a21 = __ldg(a2 + r1);
        float rm0 = __int_as_float(0x7F7FFFFF), rm1 = rm0;
        #pragma unroll
        for (int nf = 0; nf < 8; nf++) {
            const int cl = wn * 64 + nf * 8 + tg * 2;
            const int c0 = bx * 128 + cl;
            const float b20 = __ldg(b2 + c0);
            const float b21 = __ldg(b2 + c0 + 1);
            float v00 = fminf(fmaxf(a20 + b20 - 2.0f * acc[mf][nf][0], 0.f), 1.0e6f) * KSCALE;
            float v01 = fminf(fmaxf(a20 + b21 - 2.0f * acc[mf][nf][1], 0.f), 1.0e6f) * KSCALE;
            float v10 = fminf(fmaxf(a21 + b20 - 2.0f * acc[mf][nf][2], 0.f), 1.0e6f) * KSCALE;
            float v11 = fminf(fmaxf(a21 + b21 - 2.0f * acc[mf][nf][3], 0.f), 1.0e6f) * KSCALE;

            *(float2*)(Cout + (size_t)r0 * N + c0) = make_float2(v00, v01);
            *(float2*)(Cout + (size_t)r1 * N + c0) = make_float2(v10, v11);
            if (SYM && bx != by) {
                float* t0 = Cout + (size_t)c0 * N;
                float* t1 = Cout + (size_t)(c0 + 1) * N;
                t0[r0] = v00; t0[r1] = v10;
                t1[r0] = v01; t1[r1] = v11;
            }
            rm0 = fminf(rm0, fminf(v00, v01));
            rm1 = fminf(rm1, fminf(v10, v11));
            atomicMin(&sCmin[cl],     __float_as_int(fminf(v00, v10)));
            atomicMin(&sCmin[cl + 1], __float_as_int(fminf(v01, v11)));
        }
        atomicMin(&sRmin[rl0],     __float_as_int(rm0));
        atomicMin(&sRmin[rl0 + 8], __float_as_int(rm1));
    }
    __syncthreads();
    if (tid < 128) {
        atomicMin(&rminArr[rowA + tid], sRmin[tid]);
        atomicMin(&cminArr[rowB + tid], sCmin[tid]);
    }
}

// ---------------- quantize fp32 -> fp16 delta (+ optional transpose) -------
template <bool TRANS>
__global__ void quantize_kernel(const float* __restrict__ in,
                                const int* __restrict__ rminb,
                                const int* __restrict__ cminb,
                                __half* __restrict__ outN,
                                __half* __restrict__ outT)
{
    __shared__ float tile[32][33];
    const int x = blockIdx.x * 32 + threadIdx.x;
    #pragma unroll
    for (int k = 0; k < 4; k++) {
        int yy = blockIdx.y * 32 + threadIdx.y + k * 8;
        float v = __ldg(in + (size_t)yy * N + x);
        tile[threadIdx.y + k * 8][threadIdx.x] = v;
        float ref = __int_as_float(__ldg(rminb + yy));
        outN[(size_t)yy * N + x] = __float2half_rn(v - ref);
    }
    if (TRANS) {
        __syncthreads();
        const int xo = blockIdx.y * 32 + threadIdx.x;
        #pragma unroll
        for (int k = 0; k < 4; k++) {
            int yo = blockIdx.x * 32 + threadIdx.y + k * 8;
            float v = tile[threadIdx.x][threadIdx.y + k * 8];
            float ref = __int_as_float(__ldg(cminb + yo));
            outT[(size_t)yo * N + xo] = __float2half_rn(v - ref);
        }
    }
}

// ---------------- potential init ----------------
__global__ void init_pot_kernel() {
    int i = blockIdx.x * 256 + threadIdx.x;
    if (i < 3 * N) {
        (&d_F[0][0])[i] = 0.f;
        (&d_G[0][0])[i] = 0.f;
    }
}

// ---------------- matrix select ----------------
__device__ __forceinline__ void pick_mh(int p, int phase,
                                        const __half*& M, const int*& refb) {
    if (p == 0)      { M = (phase == 0) ? d_ChXY : d_ChYX; refb = (phase == 0) ? d_rmin[0] : d_rmin[1]; }
    else if (p == 1) { M = d_ChXX; refb = d_rmin[2]; }
    else             { M = d_ChYY; refb = d_rmin[3]; }
}

// ---------------- robust half-iteration (online max), fp16 matrix ----------
__device__ __forceinline__ void lse_up(float& m, float& s, float a) {
    if (a <= m) {
        s += ex2f(a - m);
    } else {
        s = fmaf(s, ex2f(m - a), 1.0f);
        m = a;
    }
}

__global__ __launch_bounds__(256) void lse_robust_kernel(int phase) {
    const int p = blockIdx.y;
    const __half* M; const int* refb;
    pick_mh(p, phase, M, refb);
    const float* vin = (phase == 0) ? d_G[p] : d_F[p];
    float* vout      = (phase == 0) ? d_F[p] : d_G[p];

    const int row = blockIdx.x;
    const float ref = __int_as_float(__ldg(refb + row));
    const int col = threadIdx.x * 16;

    float vvr[16];
    #pragma unroll
    for (int k = 0; k < 4; k++) {
        float4 t = __ldg((const float4*)(vin + col + k * 4));
        vvr[k * 4 + 0] = t.x - ref; vvr[k * 4 + 1] = t.y - ref;
        vvr[k * 4 + 2] = t.z - ref; vvr[k * 4 + 3] = t.w - ref;
    }

    const __half* Mr = M + (size_t)row * N + col;
    uint4 h0 = __ldg((const uint4*)Mr);
    uint4 h1 = __ldg((const uint4*)(Mr + 8));
    uint32_t w[8] = {h0.x, h0.y, h0.z, h0.w, h1.x, h1.y, h1.z, h1.w};

    float m = __int_as_float(0xff800000);
    float s = 0.f;
    #pragma unroll
    for (int q = 0; q < 8; q++) {
        float2 dd = __half22float2(*reinterpret_cast<__half2*>(&w[q]));
        lse_up(m, s, vvr[2 * q]     - dd.x);
        lse_up(m, s, vvr[2 * q + 1] - dd.y);
    }

    __shared__ float sm[256], ss[256];
    sm[threadIdx.x] = m;
    ss[threadIdx.x] = s;
    __syncthreads();
    for (int off = 128; off > 0; off >>= 1) {
        if (threadIdx.x < off) {
            float m1 = sm[threadIdx.x], s1 = ss[threadIdx.x];
            float m2 = sm[threadIdx.x + off], s2 = ss[threadIdx.x + off];
            float mm = fmaxf(m1, m2);
            sm[threadIdx.x] = mm;
            ss[threadIdx.x] = fmaf(s1, ex2f(m1 - mm), s2 * ex2f(m2 - mm));
        }
        __syncthreads();
    }
    if (threadIdx.x == 0) {
        // a = (v-ref)-(Cs-ref) = v-Cs: ref cancels; L = sm + log2(ss).
        float L = sm[0] + log2f(ss[0]);
        vout[row] = 12.0f - L;
        d_L[phase][p][row] = L;
    }
}

// ---------------- fast half-iteration: 8 rows/block, front-batched loads ---
#define RPB 8

template <bool STREAM>
__device__ __forceinline__ void fast_rows_body(
    const __half* __restrict__ M, const int* __restrict__ refb,
    const float* __restrict__ vin, float* __restrict__ vout,
    float* __restrict__ Lrow, int row0)
{
    const int col = threadIdx.x * 16;

    // front-batch ALL matrix loads: 16 outstanding LDG.128 per thread
    uint4 h[RPB][2];
    #pragma unroll
    for (int r = 0; r < RPB; r++) {
        const uint4* Mr = (const uint4*)(M + (size_t)(row0 + r) * N + col);
        h[r][0] = STREAM ? __ldcs(Mr)     : __ldg(Mr);
        h[r][1] = STREAM ? __ldcs(Mr + 1) : __ldg(Mr + 1);
    }

    float vv[16];
    #pragma unroll
    for (int k = 0; k < 4; k++) {
        float4 t = __ldg((const float4*)(vin + col + k * 4));
        vv[k * 4 + 0] = t.x; vv[k * 4 + 1] = t.y;
        vv[k * 4 + 2] = t.z; vv[k * 4 + 3] = t.w;
    }

    float Lp[RPB], s[RPB];
    #pragma unroll
    for (int r = 0; r < RPB; r++) Lp[r] = Lrow[row0 + r];

    #pragma unroll
    for (int r = 0; r < RPB; r++) {
        const float cr = Lp[r] + __int_as_float(__ldg(refb + row0 + r));
        uint32_t w[8] = {h[r][0].x, h[r][0].y, h[r][0].z, h[r][0].w,
                         h[r][1].x, h[r][1].y, h[r][1].z, h[r][1].w};
        float a0 = 0.f, a1 = 0.f;
        #pragma unroll
        for (int q = 0; q < 8; q++) {
            float2 dd = __half22float2(*reinterpret_cast<__half2*>(&w[q]));
            a0 += ex2f((vv[2 * q]     - cr) - dd.x);
            a1 += ex2f((vv[2 * q + 1] - cr) - dd.y);
        }
        s[r] = a0 + a1;
    }

    #pragma unroll
    for (int off = 16; off > 0; off >>= 1) {
        #pragma unroll
        for (int r = 0; r < RPB; r++)
            s[r] += __shfl_down_sync(0xffffffffu, s[r], off);
    }
    __shared__ float sw[RPB][8];
    const int lane = threadIdx.x & 31;
    const int wid  = threadIdx.x >> 5;
    if (lane == 0) {
        #pragma unroll
        for (int r = 0; r < RPB; r++) sw[r][wid] = s[r];
    }
    __syncthreads();
    if (threadIdx.x < RPB) {
        const int r = threadIdx.x;
        float S = 0.f;
        #pragma unroll
        for (int w2 = 0; w2 < 8; w2++) S += sw[r][w2];
        float Lnew = Lp[r] + log2f(S);
        vout[row0 + r] = 12.0f - Lnew;
        Lrow[row0 + r] = Lnew;
    }
}

__global__ __launch_bounds__(256) void lse_fast_kernel(int phase) {
    const int p = blockIdx.y;
    const __half* M; const int* refb;
    pick_mh(p, phase, M, refb);
    const float* vin = (phase == 0) ? d_G[p] : d_F[p];
    float* vout      = (phase == 0) ? d_F[p] : d_G[p];
    float* Lrow      = d_L[phase][p];
    const int row0   = blockIdx.x * RPB;

    if (p == 0) fast_rows_body<true >(M, refb, vin, vout, Lrow, row0);
    else        fast_rows_body<false>(M, refb, vin, vout, Lrow, row0);
}

// ---------------- final scalar reduce ----------------
__global__ __launch_bounds__(256) void final_reduce_kernel(float* __restrict__ out) {
    __shared__ double sh[3][256];
    const int tid = threadIdx.x;
    double acc0 = 0.0, acc1 = 0.0, acc2 = 0.0;
    for (int j = tid; j < N; j += 256) {
        acc0 += (double)d_F[0][j] + (double)d_G[0][j];
        acc1 += (double)d_F[1][j] + (double)d_G[1][j];
        acc2 += (double)d_F[2][j] + (double)d_G[2][j];
    }
    sh[0][tid] = acc0; sh[1][tid] = acc1; sh[2][tid] = acc2;
    __syncthreads();
    for (int off = 128; off > 0; off >>= 1) {
        if (tid < off) {
            sh[0][tid] += sh[0][tid + off];
            sh[1][tid] += sh[1][tid + off];
            sh[2][tid] += sh[2][tid + off];
        }
        __syncthreads();
    }
    if (tid == 0) {
        double Sdiff = sh[0][0] - 0.5 * (sh[1][0] + sh[2][0]);
        double val = Sdiff * OUT_SCALE;
        out[0] = (float)(val > 0.0 ? val : 0.0);
    }
}

// ---------------- launch ----------------
extern "C" void kernel_launch(void* const* d_in, const int* in_sizes, int n_in,
                              void* d_out, int out_size)
{
    const float* x = (const float*)d_in[0];
    const float* y = (const float*)d_in[1];
    float* out = (float*)d_out;

    float *Ctmp, *xsq, *ysq;
    __half *ChXY, *ChYX, *ChXX, *ChYY;
    int *rminA;
    __nv_bfloat16 *xhi, *xlo, *yhi, *ylo;
    cudaGetSymbolAddress((void**)&Ctmp, d_Ctmp);
    cudaGetSymbolAddress((void**)&ChXY, d_ChXY);
    cudaGetSymbolAddress((void**)&ChYX, d_ChYX);
    cudaGetSymbolAddress((void**)&ChXX, d_ChXX);
    cudaGetSymbolAddress((void**)&ChYY, d_ChYY);
    cudaGetSymbolAddress((void**)&rminA, d_rmin);
    cudaGetSymbolAddress((void**)&xsq, d_xsq);
    cudaGetSymbolAddress((void**)&ysq, d_ysq);
    cudaGetSymbolAddress((void**)&xhi, d_xhi);
    cudaGetSymbolAddress((void**)&xlo, d_xlo);
    cudaGetSymbolAddress((void**)&yhi, d_yhi);
    cudaGetSymbolAddress((void**)&ylo, d_ylo);

    int* rmXY = rminA + 0 * N;
    int* rmYX = rminA + 1 * N;
    int* rmXX = rminA + 2 * N;
    int* rmYY = rminA + 3 * N;

    convert_kernel<<<(N * D) / 256, 256>>>(x, xhi, xlo);
    convert_kernel<<<(N * D) / 256, 256>>>(y, yhi, ylo);

    dim3 rsBlock(32, 8);
    rowsq_kernel<<<N / 8, rsBlock>>>(x, xsq);
    rowsq_kernel<<<N / 8, rsBlock>>>(y, ysq);

    init_min_kernel<<<(4 * N + 255) / 256, 256>>>();

    dim3 qGrid(N / 32, N / 32);
    dim3 qBlock(32, 8);

    tc_gemm_kernel<false><<<NT * NT, 256>>>(xhi, xlo, yhi, ylo, xsq, ysq, Ctmp, rmXY, rmYX);
    quantize_kernel<true><<<qGrid, qBlock>>>(Ctmp, rmXY, rmYX, ChXY, ChYX);

    tc_gemm_kernel<true><<<NTRI, 256>>>(xhi, xlo, xhi, xlo, xsq, xsq, Ctmp, rmXX, rmXX);
    quantize_kernel<false><<<qGrid, qBlock>>>(Ctmp, rmXX, nullptr, ChXX, nullptr);

    tc_gemm_kernel<true><<<NTRI, 256>>>(yhi, ylo, yhi, ylo, ysq, ysq, Ctmp, rmYY, rmYY);
    quantize_kernel<false><<<qGrid, qBlock>>>(Ctmp, rmYY, nullptr, ChYY, nullptr);

    init_pot_kernel<<<(3 * N + 255) / 256, 256>>>();

    dim3 rGrid(N, 3);
    dim3 fGrid(N / RPB, 3);
    const int WARMUP = 3;
    for (int it = 0; it < WARMUP; it++) {
        lse_robust_kernel<<<rGrid, 256>>>(0);
        lse_robust_kernel<<<rGrid, 256>>>(1);
    }
    for (int it = WARMUP; it < 50; it++) {
        lse_fast_kernel<<<fGrid, 256>>>(0);
        lse_fast_kernel<<<fGrid, 256>>>(1);
    }

    final_reduce_kernel<<<1, 256>>>(out);
}